// round 1
// baseline (speedup 1.0000x reference)
#include <cuda_runtime.h>

// CapsuleRoutingPooling — algebraic collapse:
// softmax over singleton axis==1 -> coupling coeffs c == 1 for every routing
// iteration, so routing is a no-op. Output = squash(2x2 sum-pool of D=16 vecs).
//
// Shapes (fixed by setup_inputs): B=16, C=64, H=64, W=64, D=16, k=2.
// out: (B, C, 32, 32, 16) float32.

#define B_  16
#define C_  64
#define H_  64
#define W_  64
#define D_  16
#define NH_ 32
#define NW_ 32

// One thread per output float4; 4 lanes (lane&~3 group) per D=16 vector.
__global__ __launch_bounds__(256, 8)
void capsule_pool_kernel(const float4* __restrict__ in4, float4* __restrict__ out4)
{
    // total output float4s = B*C*NH*NW*4 = 4,194,304
    const unsigned gid = blockIdx.x * blockDim.x + threadIdx.x;

    const unsigned d4  = gid & 3u;        // which float4 within the D=16 vector
    const unsigned vec = gid >> 2;        // output vector index

    const unsigned nw  = vec & (NW_ - 1);
    const unsigned nh  = (vec >> 5) & (NH_ - 1);
    const unsigned bc  = vec >> 10;       // b*C + c  (0..1023)

    const unsigned h = nh * 2u;
    const unsigned w = nw * 2u;

    // float4 index into input: (((bc*H + h)*W + w)*D + 4*d4)/4 = ((bc*H+h)*W + w)*4 + d4
    const unsigned base = ((bc * H_ + h) * W_ + w) * 4u + d4;
    const unsigned rowStride = W_ * 4u;   // one h row, in float4 units

    // Streaming loads (no reuse beyond sectors in-flight): .cs hint
    float4 a0 = __ldcs(&in4[base]);               // (h,   w  )
    float4 a1 = __ldcs(&in4[base + 4u]);          // (h,   w+1)
    float4 a2 = __ldcs(&in4[base + rowStride]);   // (h+1, w  )
    float4 a3 = __ldcs(&in4[base + rowStride + 4u]); // (h+1, w+1)

    float4 s;
    s.x = (a0.x + a1.x) + (a2.x + a3.x);
    s.y = (a0.y + a1.y) + (a2.y + a3.y);
    s.z = (a0.z + a1.z) + (a2.z + a3.z);
    s.w = (a0.w + a1.w) + (a2.w + a3.w);

    // partial squared norm over this thread's 4 components
    float sq = s.x * s.x + s.y * s.y + s.z * s.z + s.w * s.w;

    // reduce across the 4-lane group (lanes differing in bits 0,1)
    sq += __shfl_xor_sync(0xFFFFFFFFu, sq, 1);
    sq += __shfl_xor_sync(0xFFFFFFFFu, sq, 2);

    // squash scale: sq/(1+sq) * 1/(sqrt(sq)+1e-8)
    const float scale = sq / (1.0f + sq) / (sqrtf(sq) + 1e-8f);

    float4 o;
    o.x = s.x * scale;
    o.y = s.y * scale;
    o.z = s.z * scale;
    o.w = s.w * scale;

    out4[vec * 4u + d4] = o;
}

extern "C" void kernel_launch(void* const* d_in, const int* in_sizes, int n_in,
                              void* d_out, int out_size)
{
    const float4* in4  = (const float4*)d_in[0];
    float4*       out4 = (float4*)d_out;

    const unsigned total_f4 = B_ * C_ * NH_ * NW_ * 4u;  // 4,194,304
    const unsigned threads  = 256;
    const unsigned blocks   = total_f4 / threads;         // 16384

    capsule_pool_kernel<<<blocks, threads>>>(in4, out4);
}